// round 12
// baseline (speedup 1.0000x reference)
#include <cuda_runtime.h>
#include <cuda_bf16.h>
#include <math.h>
#include <stdint.h>

// GaussianScorer sm_103a, 3-kernel split:
//  1) gs_prep:    g_Bh = bf16(means*inv_var), g_m2, g_logc
//  2) gs_convert: g_Ah = bf16(emb), g_e2[m] = sum_k emb^2*inv_var (exact fp32)
//  3) gs_mm:      bf16 mma.sync GEMM, B fully SMEM-resident, A via pure
//                 cp.async 4-stage ring; epilogue adds logc-0.5*m2-0.5*e2.
// Shapes: M=16384, L=128, K=512.

#define GS_M 16384
#define GS_K 512
#define GS_L 128
#define BM   128
#define BKT  64
#define NITER (GS_K / BKT)   // 8
#define NSTG 4

#define A_STAGE 16384        // 128 rows * 128B (64 bf16)
#define B_BLK   16384        // 128 L-rows * 128B per 64-k block
#define MOFF_OFF 0           // 128 f32
#define A_OFF   1024
#define B_OFF   (A_OFF + NSTG * A_STAGE)       // 66560
#define SMEM_MM (B_OFF + 8 * B_BLK)            // 197632

__device__ __nv_bfloat16 g_Ah[GS_M * GS_K];    // 16 MB bf16 emb
__device__ float g_e2[GS_M];
__device__ __nv_bfloat16 g_Bh[GS_L * GS_K];
__device__ float g_m2[GS_L];
__device__ float g_logc;

static __device__ __forceinline__ uint32_t smem_u32(const void* p) {
    uint32_t a;
    asm("{ .reg .u64 t; cvta.to.shared.u64 t, %1; cvt.u32.u64 %0, t; }" : "=r"(a) : "l"(p));
    return a;
}

#define CP_ASYNC16(dst, src) \
    asm volatile("cp.async.cg.shared.global [%0], [%1], 16;" :: "r"(dst), "l"(src) : "memory")
#define CP_COMMIT() asm volatile("cp.async.commit_group;" ::: "memory")
#define CP_WAIT2()  asm volatile("cp.async.wait_group 2;" ::: "memory")

#define LDSM_X4(r, addr)                                                        \
    asm volatile("ldmatrix.sync.aligned.m8n8.x4.shared.b16 {%0,%1,%2,%3}, [%4];" \
        : "=r"((r)[0]), "=r"((r)[1]), "=r"((r)[2]), "=r"((r)[3]) : "r"(addr))

#define MMA_BF16(d, a, b0, b1)                                                  \
    asm volatile("mma.sync.aligned.m16n8k16.row.col.f32.bf16.bf16.f32 "         \
        "{%0,%1,%2,%3}, {%4,%5,%6,%7}, {%8,%9}, {%0,%1,%2,%3};"                 \
        : "+f"((d)[0]), "+f"((d)[1]), "+f"((d)[2]), "+f"((d)[3])                \
        : "r"((a)[0]), "r"((a)[1]), "r"((a)[2]), "r"((a)[3]), "r"(b0), "r"(b1))

// 128B rows, 8 x 16B chunks, chunk ^= row&7
#define SWZ(row, chunk) ((uint32_t)((row) * 128 + (((chunk) ^ ((row) & 7)) << 4)))

// ---------------- prep ----------------
__global__ void gs_prep(const float* __restrict__ means, const float* __restrict__ var) {
    __shared__ float red[4];
    const int l = blockIdx.x;
    const int t = threadIdx.x;        // 128 threads, 4 elems each
    const int i0 = t * 4;

    float4 v4 = *(const float4*)(var + i0);
    float4 m4 = *(const float4*)(means + (size_t)l * GS_K + i0);
    float4 b4 = make_float4(m4.x / v4.x, m4.y / v4.y, m4.z / v4.z, m4.w / v4.w);

    __nv_bfloat162 p0 = __floats2bfloat162_rn(b4.x, b4.y);
    __nv_bfloat162 p1 = __floats2bfloat162_rn(b4.z, b4.w);
    *(uint2*)(g_Bh + (size_t)l * GS_K + i0) =
        make_uint2(*(uint32_t*)&p0, *(uint32_t*)&p1);

    float m2 = m4.x * b4.x + m4.y * b4.y + m4.z * b4.z + m4.w * b4.w;
    #pragma unroll
    for (int o = 16; o > 0; o >>= 1) m2 += __shfl_xor_sync(0xffffffffu, m2, o);
    if ((t & 31) == 0) red[t >> 5] = m2;
    __syncthreads();
    if (t == 0) g_m2[l] = red[0] + red[1] + red[2] + red[3];

    if (l == 0) {
        __syncthreads();
        float lg = logf(v4.x) + logf(v4.y) + logf(v4.z) + logf(v4.w);
        #pragma unroll
        for (int o = 16; o > 0; o >>= 1) lg += __shfl_xor_sync(0xffffffffu, lg, o);
        if ((t & 31) == 0) red[t >> 5] = lg;
        __syncthreads();
        if (t == 0) {
            const float FACTOR = -256.0f * 1.8378770664093453f;   // -E/2 * ln(2*pi)
            g_logc = FACTOR - 0.5f * (red[0] + red[1] + red[2] + red[3]);
        }
    }
}

// ---------------- convert: emb -> bf16 + exact e2 ----------------
__global__ __launch_bounds__(256)
void gs_convert(const float* __restrict__ emb, const float* __restrict__ var) {
    const int row = (blockIdx.x << 3) + (threadIdx.x >> 5);
    const int lane = threadIdx.x & 31;

    const float* src = emb + (size_t)row * GS_K + lane * 16;
    float4 a0 = *(const float4*)(src);
    float4 a1 = *(const float4*)(src + 4);
    float4 a2 = *(const float4*)(src + 8);
    float4 a3 = *(const float4*)(src + 12);

    const float* vp = var + lane * 16;
    float4 v0 = *(const float4*)(vp);
    float4 v1 = *(const float4*)(vp + 4);
    float4 v2 = *(const float4*)(vp + 8);
    float4 v3 = *(const float4*)(vp + 12);

    float e2 = 0.0f;
    e2 = fmaf(a0.x * a0.x, 1.0f / v0.x, e2);
    e2 = fmaf(a0.y * a0.y, 1.0f / v0.y, e2);
    e2 = fmaf(a0.z * a0.z, 1.0f / v0.z, e2);
    e2 = fmaf(a0.w * a0.w, 1.0f / v0.w, e2);
    e2 = fmaf(a1.x * a1.x, 1.0f / v1.x, e2);
    e2 = fmaf(a1.y * a1.y, 1.0f / v1.y, e2);
    e2 = fmaf(a1.z * a1.z, 1.0f / v1.z, e2);
    e2 = fmaf(a1.w * a1.w, 1.0f / v1.w, e2);
    e2 = fmaf(a2.x * a2.x, 1.0f / v2.x, e2);
    e2 = fmaf(a2.y * a2.y, 1.0f / v2.y, e2);
    e2 = fmaf(a2.z * a2.z, 1.0f / v2.z, e2);
    e2 = fmaf(a2.w * a2.w, 1.0f / v2.w, e2);
    e2 = fmaf(a3.x * a3.x, 1.0f / v3.x, e2);
    e2 = fmaf(a3.y * a3.y, 1.0f / v3.y, e2);
    e2 = fmaf(a3.z * a3.z, 1.0f / v3.z, e2);
    e2 = fmaf(a3.w * a3.w, 1.0f / v3.w, e2);

    __nv_bfloat162 c0 = __floats2bfloat162_rn(a0.x, a0.y);
    __nv_bfloat162 c1 = __floats2bfloat162_rn(a0.z, a0.w);
    __nv_bfloat162 c2 = __floats2bfloat162_rn(a1.x, a1.y);
    __nv_bfloat162 c3 = __floats2bfloat162_rn(a1.z, a1.w);
    __nv_bfloat162 c4 = __floats2bfloat162_rn(a2.x, a2.y);
    __nv_bfloat162 c5 = __floats2bfloat162_rn(a2.z, a2.w);
    __nv_bfloat162 c6 = __floats2bfloat162_rn(a3.x, a3.y);
    __nv_bfloat162 c7 = __floats2bfloat162_rn(a3.z, a3.w);

    __nv_bfloat16* dst = g_Ah + (size_t)row * GS_K + lane * 16;
    *(uint4*)(dst) = make_uint4(*(uint32_t*)&c0, *(uint32_t*)&c1,
                                *(uint32_t*)&c2, *(uint32_t*)&c3);
    *(uint4*)(dst + 8) = make_uint4(*(uint32_t*)&c4, *(uint32_t*)&c5,
                                    *(uint32_t*)&c6, *(uint32_t*)&c7);

    #pragma unroll
    for (int o = 16; o > 0; o >>= 1) e2 += __shfl_xor_sync(0xffffffffu, e2, o);
    if (lane == 0) g_e2[row] = e2;
}

// ---------------- GEMM: B resident, A cp.async ring ----------------
__global__ __launch_bounds__(512, 1)
void gs_mm(float* __restrict__ out) {
    extern __shared__ __align__(1024) char smem[];
    const uint32_t sb = smem_u32(smem);
    const int tid = threadIdx.x;
    const int m0 = blockIdx.x * BM;

    const int r = tid >> 2;           // 0..127
    const int q = tid & 3;
    const uint32_t d0 = SWZ(r, 2 * q);
    const uint32_t d1 = SWZ(r, 2 * q + 1);

    // B: all 8 k-blocks resident (one commit group)
    const char* bsrc = (const char*)(g_Bh + (size_t)r * GS_K);
    #pragma unroll
    for (int b = 0; b < 8; b++) {
        CP_ASYNC16(sb + B_OFF + b * B_BLK + d0, bsrc + (b * 64 + q * 16) * 2);
        CP_ASYNC16(sb + B_OFF + b * B_BLK + d1, bsrc + (b * 64 + q * 16 + 8) * 2);
    }
    CP_COMMIT();

    // A: stages 0..2
    const char* asrc = (const char*)(g_Ah + (size_t)(m0 + r) * GS_K);
    #pragma unroll
    for (int s = 0; s < 3; s++) {
        CP_ASYNC16(sb + A_OFF + s * A_STAGE + d0, asrc + (s * BKT + q * 16) * 2);
        CP_ASYNC16(sb + A_OFF + s * A_STAGE + d1, asrc + (s * BKT + q * 16 + 8) * 2);
        CP_COMMIT();
    }

    if (tid < 128)
        ((float*)(smem + MOFF_OFF))[tid] = g_logc - 0.5f * g_m2[tid];

    const int lane = tid & 31;
    const int g = lane >> 2;
    const int tig = lane & 3;
    const int wid = tid >> 5;         // 0..15
    const int wm = wid >> 2;          // 0..3 -> 32 rows
    const int wn = wid & 3;           // 0..3 -> 32 cols
    const int mm = lane >> 3;
    const int mrow = lane & 7;

    const int rowA0 = wm * 32 + (mm & 1) * 8 + mrow;
    const int rowB0 = wn * 32 + (mm >> 1) * 8 + mrow;
    const int cA = mm >> 1;
    const int cB = mm & 1;

    float acc[2][4][4];
    #pragma unroll
    for (int mt = 0; mt < 2; mt++)
        #pragma unroll
        for (int nt = 0; nt < 4; nt++)
            #pragma unroll
            for (int j = 0; j < 4; j++) acc[mt][nt][j] = 0.0f;

    #pragma unroll
    for (int it = 0; it < NITER; ++it) {
        CP_WAIT2();
        __syncthreads();              // stage it (and B on it=0) visible; prior reads done

        if (it + 3 < NITER) {
            const int s = (it + 3) & (NSTG - 1);
            CP_ASYNC16(sb + A_OFF + s * A_STAGE + d0, asrc + ((it + 3) * BKT + q * 16) * 2);
            CP_ASYNC16(sb + A_OFF + s * A_STAGE + d1, asrc + ((it + 3) * BKT + q * 16 + 8) * 2);
            CP_COMMIT();
        } else {
            CP_COMMIT();
        }

        const uint32_t As = sb + A_OFF + (it & (NSTG - 1)) * A_STAGE;
        const uint32_t Bs = sb + B_OFF + it * B_BLK;

        #pragma unroll
        for (int ks = 0; ks < 4; ks++) {
            const int c0 = ks * 2;
            uint32_t af[2][4], bq[2][4];
            LDSM_X4(af[0], As + SWZ(rowA0,      c0 + cA));
            LDSM_X4(af[1], As + SWZ(rowA0 + 16, c0 + cA));
            LDSM_X4(bq[0], Bs + SWZ(rowB0,      c0 + cB));
            LDSM_X4(bq[1], Bs + SWZ(rowB0 + 16, c0 + cB));
            #pragma unroll
            for (int mt = 0; mt < 2; mt++) {
                MMA_BF16(acc[mt][0], af[mt], bq[0][0], bq[0][1]);
                MMA_BF16(acc[mt][1], af[mt], bq[0][2], bq[0][3]);
                MMA_BF16(acc[mt][2], af[mt], bq[1][0], bq[1][1]);
                MMA_BF16(acc[mt][3], af[mt], bq[1][2], bq[1][3]);
            }
        }
    }

    const float* moff = (const float*)(smem + MOFF_OFF);

    #pragma unroll
    for (int mt = 0; mt < 2; mt++) {
        const int r0 = wm * 32 + mt * 16 + g;
        const float rb0 = -0.5f * g_e2[m0 + r0];
        const float rb1 = -0.5f * g_e2[m0 + r0 + 8];
        float* orow0 = out + (size_t)(m0 + r0) * GS_L;
        float* orow1 = orow0 + 8 * GS_L;
        #pragma unroll
        for (int nt = 0; nt < 4; nt++) {
            const int col = wn * 32 + nt * 8 + tig * 2;
            float2 mo = *(const float2*)(moff + col);
            float2 o0, o1;
            o0.x = acc[mt][nt][0] + rb0 + mo.x;
            o0.y = acc[mt][nt][1] + rb0 + mo.y;
            o1.x = acc[mt][nt][2] + rb1 + mo.x;
            o1.y = acc[mt][nt][3] + rb1 + mo.y;
            *(float2*)(orow0 + col) = o0;
            *(float2*)(orow1 + col) = o1;
        }
    }
}

extern "C" void kernel_launch(void* const* d_in, const int* in_sizes, int n_in,
                              void* d_out, int out_size) {
    const float* emb   = (const float*)d_in[0];   // [8, 2048, 512] f32
    const float* means = (const float*)d_in[1];   // [128, 512] f32
    const float* var   = (const float*)d_in[2];   // [512] f32
    float* out = (float*)d_out;                   // [8, 2048, 128] f32
    (void)in_sizes; (void)n_in; (void)out_size;

    cudaFuncSetAttribute(gs_mm, cudaFuncAttributeMaxDynamicSharedMemorySize, SMEM_MM);
    gs_prep<<<GS_L, 128>>>(means, var);
    gs_convert<<<GS_M / 8, 256>>>(emb, var);
    gs_mm<<<GS_M / BM, 512, SMEM_MM>>>(out);
}

// round 13
// speedup vs baseline: 1.2622x; 1.2622x over previous
#include <cuda_runtime.h>
#include <cuda_bf16.h>
#include <math.h>
#include <stdint.h>

// GaussianScorer sm_103a: bf16 mma.sync m16n8k16 + ldmatrix + cp.async.
// BM=128, BK=32, 5-stage ring, 256 threads, __launch_bounds__(256,2)
// -> 2 CTAs/SM co-residency. 8 warps, 64x32 warp tiles.
// out[m,l] = logc - 0.5*e2[m] - 0.5*m2[l] + cross[m,l]
// Shapes: M=16384, L=128, K=512.

#define GS_M 16384
#define GS_K 512
#define GS_L 128
#define BM   128
#define BKT  32
#define NITER (GS_K / BKT)   // 16
#define NSTG 5
#define NTHREADS 256

#define A_STAGE 8192                 // 128 rows * 64B (32 bf16)
#define B_STAGE 8192
#define IV_OFF   0                   // 512 f32
#define MOFF_OFF 2048                // 128 f32: logc - 0.5*m2[l]
#define E2_OFF   2560                // 2*128 f32 partials
#define A_OFF    4096
#define B_OFF    (A_OFF + NSTG * A_STAGE)     // 45056
#define SMEM_TOTAL (B_OFF + NSTG * B_STAGE)   // 86016  (x2 CTAs = 172032 < 228KB)

__device__ __nv_bfloat16 g_Bh[GS_L * GS_K];
__device__ float g_m2[GS_L];
__device__ float g_logc;

static __device__ __forceinline__ uint32_t smem_u32(const void* p) {
    uint32_t a;
    asm("{ .reg .u64 t; cvta.to.shared.u64 t, %1; cvt.u32.u64 %0, t; }" : "=r"(a) : "l"(p));
    return a;
}

#define CP_ASYNC16(dst, src) \
    asm volatile("cp.async.cg.shared.global [%0], [%1], 16;" :: "r"(dst), "l"(src) : "memory")
#define CP_COMMIT() asm volatile("cp.async.commit_group;" ::: "memory")
#define CP_WAIT3()  asm volatile("cp.async.wait_group 3;" ::: "memory")

#define LDSM_X4(r, addr)                                                        \
    asm volatile("ldmatrix.sync.aligned.m8n8.x4.shared.b16 {%0,%1,%2,%3}, [%4];" \
        : "=r"((r)[0]), "=r"((r)[1]), "=r"((r)[2]), "=r"((r)[3]) : "r"(addr))

#define MMA_BF16(d, a, b0, b1)                                                  \
    asm volatile("mma.sync.aligned.m16n8k16.row.col.f32.bf16.bf16.f32 "         \
        "{%0,%1,%2,%3}, {%4,%5,%6,%7}, {%8,%9}, {%0,%1,%2,%3};"                 \
        : "+f"((d)[0]), "+f"((d)[1]), "+f"((d)[2]), "+f"((d)[3])                \
        : "r"((a)[0]), "r"((a)[1]), "r"((a)[2]), "r"((a)[3]), "r"(b0), "r"(b1))

// 64B rows, 4 x 16B chunks, chunk ^= (row>>1)&3   (same as R5 best kernel)
#define SWZ(row, chunk) ((uint32_t)((row) * 64 + (((chunk) ^ (((row) >> 1) & 3)) << 4)))

// ---------------- prep: g_Bh = bf16(means*inv_var), g_m2, g_logc ----------------
__global__ void gs_prep(const float* __restrict__ means, const float* __restrict__ var) {
    __shared__ float red[4];
    const int l = blockIdx.x;
    const int t = threadIdx.x;        // 128 threads, 4 elems each
    const int i0 = t * 4;

    float4 v4 = *(const float4*)(var + i0);
    float4 m4 = *(const float4*)(means + (size_t)l * GS_K + i0);
    float4 b4 = make_float4(__fdividef(m4.x, v4.x), __fdividef(m4.y, v4.y),
                            __fdividef(m4.z, v4.z), __fdividef(m4.w, v4.w));

    __nv_bfloat162 p0 = __floats2bfloat162_rn(b4.x, b4.y);
    __nv_bfloat162 p1 = __floats2bfloat162_rn(b4.z, b4.w);
    *(uint2*)(g_Bh + (size_t)l * GS_K + i0) =
        make_uint2(*(uint32_t*)&p0, *(uint32_t*)&p1);

    float m2 = m4.x * b4.x + m4.y * b4.y + m4.z * b4.z + m4.w * b4.w;
    #pragma unroll
    for (int o = 16; o > 0; o >>= 1) m2 += __shfl_xor_sync(0xffffffffu, m2, o);
    if ((t & 31) == 0) red[t >> 5] = m2;
    __syncthreads();
    if (t == 0) g_m2[l] = red[0] + red[1] + red[2] + red[3];

    if (l == 0) {
        __syncthreads();
        float lg = __logf(v4.x) + __logf(v4.y) + __logf(v4.z) + __logf(v4.w);
        #pragma unroll
        for (int o = 16; o > 0; o >>= 1) lg += __shfl_xor_sync(0xffffffffu, lg, o);
        if ((t & 31) == 0) red[t >> 5] = lg;
        __syncthreads();
        if (t == 0) {
            const float FACTOR = -256.0f * 1.8378770664093453f;   // -E/2 * ln(2*pi)
            g_logc = FACTOR - 0.5f * (red[0] + red[1] + red[2] + red[3]);
        }
    }
}

// ---------------- main kernel ----------------
__global__ __launch_bounds__(NTHREADS, 2)
void gs_main(const float* __restrict__ emb, const float* __restrict__ var,
             float* __restrict__ out) {
    extern __shared__ __align__(1024) char smem[];
    const uint32_t sb = smem_u32(smem);
    const int tid = threadIdx.x;
    const int m0 = blockIdx.x * BM;

    const int lane = tid & 31;
    const int g = lane >> 2;          // 0..7
    const int tig = lane & 3;         // 0..3
    const int wid = tid >> 5;         // 0..7
    const int wm = wid >> 2;          // 0..1 -> 64 rows
    const int wn = wid & 3;           // 0..3 -> 32 cols
    const int mm = lane >> 3;         // ldmatrix matrix id 0..3
    const int mrow = lane & 7;

    // producer mapping: thread owns (row, 16-k half) of a 128x32 stage
    const int arow = tid >> 1;        // 0..127
    const int ah = tid & 1;           // 0..1
    const uint32_t sts0 = SWZ(arow, ah * 2);
    const uint32_t sts1 = SWZ(arow, ah * 2 + 1);

    // per-block constants into smem
    if (tid < 128) {
        float4 v4 = *(const float4*)(var + tid * 4);
        *(float4*)(smem + IV_OFF + tid * 16) =
            make_float4(1.0f / v4.x, 1.0f / v4.y, 1.0f / v4.z, 1.0f / v4.w);
        ((float*)(smem + MOFF_OFF))[tid] = g_logc - 0.5f * g_m2[tid];
    }

    const float* aSrc = emb + (size_t)(m0 + arow) * GS_K + ah * 16;
    const __nv_bfloat16* bSrc = g_Bh + (size_t)arow * GS_K + ah * 16;

    #define LDG_A(rr, kt) do {                                                   \
        rr[0] = *(const float4*)(aSrc + (kt));                                   \
        rr[1] = *(const float4*)(aSrc + (kt) + 4);                               \
        rr[2] = *(const float4*)(aSrc + (kt) + 8);                               \
        rr[3] = *(const float4*)(aSrc + (kt) + 12);                              \
    } while (0)

    #define CPASYNC_B(s, kt) do {                                               \
        const uint32_t _bb = sb + B_OFF + (s) * B_STAGE;                        \
        CP_ASYNC16(_bb + sts0, (const char*)(bSrc + (kt)));                     \
        CP_ASYNC16(_bb + sts1, (const char*)(bSrc + (kt) + 8));                 \
        CP_COMMIT();                                                            \
    } while (0)

    // convert + store A half-row (2 x STS.128), exact fp32 e2
    #define STS_A_E2(s, rr, kt) do {                                            \
        const float* _iv = (const float*)(smem + IV_OFF) + (kt) + ah * 16;      \
        _Pragma("unroll")                                                       \
        for (int _q = 0; _q < 4; _q++) {                                        \
            float4 _v = *(const float4*)(_iv + _q * 4);                         \
            e2p = fmaf(rr[_q].x * rr[_q].x, _v.x, e2p);                         \
            e2p = fmaf(rr[_q].y * rr[_q].y, _v.y, e2p);                         \
            e2p = fmaf(rr[_q].z * rr[_q].z, _v.z, e2p);                         \
            e2p = fmaf(rr[_q].w * rr[_q].w, _v.w, e2p);                         \
        }                                                                       \
        __nv_bfloat162 _c0 = __floats2bfloat162_rn(rr[0].x, rr[0].y);           \
        __nv_bfloat162 _c1 = __floats2bfloat162_rn(rr[0].z, rr[0].w);           \
        __nv_bfloat162 _c2 = __floats2bfloat162_rn(rr[1].x, rr[1].y);           \
        __nv_bfloat162 _c3 = __floats2bfloat162_rn(rr[1].z, rr[1].w);           \
        __nv_bfloat162 _c4 = __floats2bfloat162_rn(rr[2].x, rr[2].y);           \
        __nv_bfloat162 _c5 = __floats2bfloat162_rn(rr[2].z, rr[2].w);           \
        __nv_bfloat162 _c6 = __floats2bfloat162_rn(rr[3].x, rr[3].y);           \
        __nv_bfloat162 _c7 = __floats2bfloat162_rn(rr[3].z, rr[3].w);           \
        const uint32_t _ao = A_OFF + (s) * A_STAGE;                             \
        *(uint4*)(smem + _ao + sts0) =                                          \
            make_uint4(*(uint32_t*)&_c0, *(uint32_t*)&_c1,                      \
                       *(uint32_t*)&_c2, *(uint32_t*)&_c3);                     \
        *(uint4*)(smem + _ao + sts1) =                                          \
            make_uint4(*(uint32_t*)&_c4, *(uint32_t*)&_c5,                      \
                       *(uint32_t*)&_c6, *(uint32_t*)&_c7);                     \
    } while (0)

    float e2p = 0.0f;
    float4 rA[4];

    // ---- prologue: B stages 0..3 ; A stage 0 ----
    CPASYNC_B(0, 0);
    CPASYNC_B(1, BKT);
    CPASYNC_B(2, 2 * BKT);
    CPASYNC_B(3, 3 * BKT);
    LDG_A(rA, 0);
    __syncthreads();                  // IV table ready before e2 use
    STS_A_E2(0, rA, 0);
    LDG_A(rA, BKT);                   // A for stage 1, stored at end of iter 0

    float acc[4][4][4];
    #pragma unroll
    for (int mt = 0; mt < 4; mt++)
        #pragma unroll
        for (int nt = 0; nt < 4; nt++)
            #pragma unroll
            for (int j = 0; j < 4; j++) acc[mt][nt][j] = 0.0f;

    const int rowAb = wm * 64 + (mm & 1) * 8 + mrow;   // +16*mt
    const int rowBb = wn * 32 + (mm >> 1) * 8 + mrow;  // +16 for pair 1
    const int cA = mm >> 1;
    const int cB = mm & 1;

    #pragma unroll
    for (int it = 0; it < NITER; ++it) {
        CP_WAIT3();
        __syncthreads();              // stage it (A STS + B cp.async) visible

        if (it + 4 < NITER) { CPASYNC_B((it + 4) % NSTG, (it + 4) * BKT); }
        else                { CP_COMMIT(); }

        const uint32_t As = sb + A_OFF + (it % NSTG) * A_STAGE;
        const uint32_t Bs = sb + B_OFF + (it % NSTG) * B_STAGE;

        #pragma unroll
        for (int ks = 0; ks < 2; ks++) {
            const int c0 = ks * 2;
            uint32_t af[4][4], bq[2][4];
            LDSM_X4(af[0], As + SWZ(rowAb,      c0 + cA));
            LDSM_X4(af[1], As + SWZ(rowAb + 16, c0 + cA));
            LDSM_X4(af[2], As + SWZ(rowAb + 32, c0 + cA));
            LDSM_X4(af[3], As + SWZ(rowAb + 48, c0 + cA));
            LDSM_X4(bq[0], Bs + SWZ(rowBb,      c0 + cB));
            LDSM_X4(bq[1], Bs + SWZ(rowBb + 16, c0 + cB));
            #pragma unroll
            for (int mt = 0; mt < 4; mt++) {
                MMA_BF16(acc[mt][0], af[mt], bq[0][0], bq[0][1]);
                MMA_BF16(acc[mt][1], af[mt], bq[0][2], bq[0][3]);
                MMA_BF16(acc[mt][2], af[mt], bq[1][0], bq[1][1]);
                MMA_BF16(acc[mt][3], af[mt], bq[1][2], bq[1][3]);
            }
        }

        if (it + 1 < NITER) {
            STS_A_E2((it + 1) % NSTG, rA, (it + 1) * BKT);   // stage it+1 ready at next bar
            if (it + 2 < NITER) LDG_A(rA, (it + 2) * BKT);   // refill regs for next tail
        }
    }

    // ---- e2 combine ----
    ((float*)(smem + E2_OFF))[ah * 128 + arow] = e2p;
    __syncthreads();
    const float* sE2 = (const float*)(smem + E2_OFF);
    const float* moff = (const float*)(smem + MOFF_OFF);

    // ---- epilogue ----
    #pragma unroll
    for (int mt = 0; mt < 4; mt++) {
        const int r0 = wm * 64 + mt * 16 + g;
        const float rb0 = -0.5f * (sE2[r0] + sE2[128 + r0]);
        const float rb1 = -0.5f * (sE2[r0 + 8] + sE2[128 + r0 + 8]);
        float* orow0 = out + (size_t)(m0 + r0) * GS_L;
        float* orow1 = orow0 + 8 * GS_L;
        #pragma unroll
        for (int nt = 0; nt < 4; nt++) {
            const int col = wn * 32 + nt * 8 + tig * 2;
            float2 mo = *(const float2*)(moff + col);
            float2 o0, o1;
            o0.x = acc[mt][nt][0] + rb0 + mo.x;
            o0.y = acc[mt][nt][1] + rb0 + mo.y;
            o1.x = acc[mt][nt][2] + rb1 + mo.x;
            o1.y = acc[mt][nt][3] + rb1 + mo.y;
            *(float2*)(orow0 + col) = o0;
            *(float2*)(orow1 + col) = o1;
        }
    }
}

extern "C" void kernel_launch(void* const* d_in, const int* in_sizes, int n_in,
                              void* d_out, int out_size) {
    const float* emb   = (const float*)d_in[0];   // [8, 2048, 512] f32
    const float* means = (const float*)d_in[1];   // [128, 512] f32
    const float* var   = (const float*)d_in[2];   // [512] f32
    float* out = (float*)d_out;                   // [8, 2048, 128] f32
    (void)in_sizes; (void)n_in; (void)out_size;

    cudaFuncSetAttribute(gs_main, cudaFuncAttributeMaxDynamicSharedMemorySize, SMEM_TOTAL);
    gs_prep<<<GS_L, 128>>>(means, var);
    gs_main<<<GS_M / BM, NTHREADS, SMEM_TOTAL>>>(emb, var, out);
}